// round 14
// baseline (speedup 1.0000x reference)
#include <cuda_runtime.h>
#include <cuda_bf16.h>

// CSR multi-head SpMM: out[n,h,d] = sum_{e in row n} ew[e,h] * nf[col[e],h,d]
// N=50000, E=800000, H=8, D=8 -> 64 floats per row.
//
// R12/R13: nnz-balanced 32-edge tiles (validated), PAIR-EDGE inner loop:
// lanes 0-15 process even edges, lanes 16-31 odd edges; sub-lane s owns
// float4 (elements 4s..4s+3, head h=s>>1). One step = 2 edges with one
// LDG.128 gather + one weight LDG + one col LDS + 4 FMA -> ~6 instr/edge
// (was ~9.4). CSR dst is monotonic, so the warp-uniform window check
// sdst[2t+3]!=sdst[2t] guarantees each half's accumulation run touches one
// row; all flushes are atomic (4 scalar REDs/lane, rare: ~3/tile).
// fill_dst (warp per row) also zeroes the output row -> memset node removed.

#define H 8
#define D 8
#define ROW_ELEMS (H * D)
#define TILE 32
#define STEPS 16
#define WPB 4            // warps per block in spmm kernel
#define MAX_EDGES 800000
#define FULLMASK 0xffffffffu

__device__ int g_dst[MAX_EDGES];

__global__ __launch_bounds__(256) void fill_dst_kernel(
    const int* __restrict__ row_ptr, float* __restrict__ out, int n_nodes)
{
    int warp = (blockIdx.x * blockDim.x + threadIdx.x) >> 5;
    int lane = threadIdx.x & 31;
    if (warp >= n_nodes) return;

    // zero this row of the output (accumulation target)
    float2 z; z.x = 0.0f; z.y = 0.0f;
    *reinterpret_cast<float2*>(out + (size_t)warp * ROW_ELEMS + lane * 2) = z;

    int s = __ldg(&row_ptr[warp]);
    int e = __ldg(&row_ptr[warp + 1]);
    for (int j = s + lane; j < e; j += 32)
        g_dst[j] = warp;                    // coalesced, fire-and-forget
}

__global__ __launch_bounds__(32 * WPB) void spmm_balanced_kernel(
    const int* __restrict__ col_idx,
    const float* __restrict__ edge_weight,   // [E, 8]
    const float* __restrict__ node_feat,     // [N, 64]
    float* __restrict__ out,                 // [N, 64]
    int n_edges)
{
    __shared__ int sdst[WPB][TILE + 2];
    __shared__ int scol[WPB][TILE];

    int wip  = threadIdx.x >> 5;
    int lane = threadIdx.x & 31;
    int tile = blockIdx.x * WPB + wip;
    int base = tile * TILE;
    if (base >= n_edges) return;

    // stage this tile's 32 columns + 32 destination rows (coalesced)
    int e   = base + lane;
    int idx = (e < n_edges) ? e : (n_edges - 1);
    int my_col = __ldg(&col_idx[idx]);
    int my_dst = __ldg(&g_dst[idx]);
    scol[wip][lane] = my_col;
    sdst[wip][lane] = my_dst;
    int last = __shfl_sync(FULLMASK, my_dst, 31);   // stage-time only
    if (lane < 2) sdst[wip][TILE + lane] = last;    // pad for window check
    __syncwarp();

    int half = lane >> 4;          // 0: even edges, 1: odd edges
    int s    = lane & 15;          // sub-lane: owns floats [4s, 4s+3]
    int h    = s >> 1;             // head index of this float4
    float ax = 0.f, ay = 0.f, az = 0.f, aw = 0.f;

    if (base + TILE <= n_edges) {
        #pragma unroll 4
        for (int t = 0; t < STEPS; ++t) {
            int j   = 2 * t + half;
            int c   = scol[wip][j];                       // LDS (2 values/warp)
            float w = __ldg(&edge_weight[(size_t)(base + j) * H + h]);
            float4 f = *reinterpret_cast<const float4*>(
                node_feat + (size_t)c * ROW_ELEMS + s * 4);
            ax = fmaf(w, f.x, ax);
            ay = fmaf(w, f.y, ay);
            az = fmaf(w, f.z, az);
            aw = fmaf(w, f.w, aw);
            // warp-uniform flush: any dst change in window [2t, 2t+3]
            // (dst monotonic -> each half's run is single-row)
            if (t == STEPS - 1 || sdst[wip][2 * t + 3] != sdst[wip][2 * t]) {
                int drow = sdst[wip][j];                  // this half's row
                float* o = out + (size_t)drow * ROW_ELEMS + s * 4;
                atomicAdd(o,     ax);
                atomicAdd(o + 1, ay);
                atomicAdd(o + 2, az);
                atomicAdd(o + 3, aw);
                ax = 0.f; ay = 0.f; az = 0.f; aw = 0.f;
            }
        }
    } else {
        // tail tile (not hit when E % 32 == 0): half 0 only, per-edge atomics
        if (half == 0) {
            int nb = n_edges - base;
            for (int j = 0; j < nb; ++j) {
                int c   = scol[wip][j];
                float w = __ldg(&edge_weight[(size_t)(base + j) * H + h]);
                float4 f = *reinterpret_cast<const float4*>(
                    node_feat + (size_t)c * ROW_ELEMS + s * 4);
                int drow = sdst[wip][j];
                float* o = out + (size_t)drow * ROW_ELEMS + s * 4;
                atomicAdd(o,     w * f.x);
                atomicAdd(o + 1, w * f.y);
                atomicAdd(o + 2, w * f.z);
                atomicAdd(o + 3, w * f.w);
            }
        }
    }
}

extern "C" void kernel_launch(void* const* d_in, const int* in_sizes, int n_in,
                              void* d_out, int out_size)
{
    const int*   row_ptr     = (const int*)d_in[0];
    const int*   col_idx     = (const int*)d_in[1];
    const float* edge_weight = (const float*)d_in[2];
    const float* node_feat   = (const float*)d_in[3];
    float*       out         = (float*)d_out;

    int n_nodes = in_sizes[0] - 1;   // row_ptr has N+1 entries
    int n_edges = in_sizes[1];       // col_idx element count

    // k1: zero output rows + per-edge destination rows (warp per row)
    int b1 = (n_nodes * 32 + 255) / 256;
    fill_dst_kernel<<<b1, 256>>>(row_ptr, out, n_nodes);

    // k2: balanced pair-edge tile SpMM
    int tiles = (n_edges + TILE - 1) / TILE;
    int b2 = (tiles + WPB - 1) / WPB;
    spmm_balanced_kernel<<<b2, 32 * WPB>>>(col_idx, edge_weight,
                                           node_feat, out, n_edges);
}

// round 15
// speedup vs baseline: 1.5067x; 1.5067x over previous
#include <cuda_runtime.h>
#include <cuda_bf16.h>

// CSR multi-head SpMM: out[n,h,d] = sum_{e in row n} ew[e,h] * nf[col[e],h,d]
// N=50000, E=800000, H=8, D=8 -> 64 floats per row.
//
// R14 = R11's validated balanced spmm body (ncu 29.4us, occ 82%, issue 47%)
//   + fill_dst fused with output zeroing (memset node removed)
//   + float2 vector atomicAdd at segment flush (RED.64: 1 op/lane, was 2).
// R12/R13 pair-edge REVERTED (flush-window doubled RED count and two halves
// serialized on identical atomic addresses: L2 52%, spmm 40.8us).

#define H 8
#define D 8
#define ROW_ELEMS (H * D)
#define TILE 32
#define WPB 4            // warps per block in spmm kernel
#define MAX_EDGES 800000

__device__ int g_dst[MAX_EDGES];

__global__ __launch_bounds__(256) void fill_dst_kernel(
    const int* __restrict__ row_ptr, float* __restrict__ out, int n_nodes)
{
    int warp = (blockIdx.x * blockDim.x + threadIdx.x) >> 5;
    int lane = threadIdx.x & 31;
    if (warp >= n_nodes) return;

    // zero this output row (accumulation target) - replaces memset node
    float2 z; z.x = 0.0f; z.y = 0.0f;
    *reinterpret_cast<float2*>(out + (size_t)warp * ROW_ELEMS + lane * 2) = z;

    int s = __ldg(&row_ptr[warp]);
    int e = __ldg(&row_ptr[warp + 1]);
    for (int j = s + lane; j < e; j += 32)
        g_dst[j] = warp;                    // coalesced, fire-and-forget
}

__global__ __launch_bounds__(32 * WPB) void spmm_balanced_kernel(
    const int* __restrict__ col_idx,
    const float* __restrict__ edge_weight,   // [E, 8]
    const float* __restrict__ node_feat,     // [N, 64]
    float* __restrict__ out,                 // [N, 64]
    int n_edges)
{
    __shared__ int sdst[WPB][TILE];
    __shared__ int scol[WPB][TILE];

    int wip  = threadIdx.x >> 5;
    int lane = threadIdx.x & 31;
    int tile = blockIdx.x * WPB + wip;
    int base = tile * TILE;
    if (base >= n_edges) return;

    // stage this tile's 32 column indices + 32 destination rows (coalesced)
    int e   = base + lane;
    int idx = (e < n_edges) ? e : (n_edges - 1);
    scol[wip][lane] = __ldg(&col_idx[idx]);
    sdst[wip][lane] = __ldg(&g_dst[idx]);
    __syncwarp();

    int h = lane >> 2;
    float ax = 0.0f, ay = 0.0f;

    if (base + TILE <= n_edges) {
        // full tile: compile-time bound keeps load batching intact
        #pragma unroll 4
        for (int j = 0; j < TILE; ++j) {
            int c   = scol[wip][j];                       // LDS broadcast
            float w = __ldg(&edge_weight[(size_t)(base + j) * H + h]);
            float2 f = *reinterpret_cast<const float2*>(
                node_feat + (size_t)c * ROW_ELEMS + lane * 2);
            ax = fmaf(w, f.x, ax);
            ay = fmaf(w, f.y, ay);
            // warp-uniform flush at segment boundary / tile end
            if (j == TILE - 1 || sdst[wip][j + 1] != sdst[wip][j]) {
                float2 v; v.x = ax; v.y = ay;
                atomicAdd(reinterpret_cast<float2*>(
                    out + (size_t)sdst[wip][j] * ROW_ELEMS + lane * 2), v);
                ax = 0.0f; ay = 0.0f;
            }
        }
    } else {
        int nb = n_edges - base;
        for (int j = 0; j < nb; ++j) {
            int c   = scol[wip][j];
            float w = __ldg(&edge_weight[(size_t)(base + j) * H + h]);
            float2 f = *reinterpret_cast<const float2*>(
                node_feat + (size_t)c * ROW_ELEMS + lane * 2);
            ax = fmaf(w, f.x, ax);
            ay = fmaf(w, f.y, ay);
            if (j == nb - 1 || sdst[wip][j + 1] != sdst[wip][j]) {
                float2 v; v.x = ax; v.y = ay;
                atomicAdd(reinterpret_cast<float2*>(
                    out + (size_t)sdst[wip][j] * ROW_ELEMS + lane * 2), v);
                ax = 0.0f; ay = 0.0f;
            }
        }
    }
}

extern "C" void kernel_launch(void* const* d_in, const int* in_sizes, int n_in,
                              void* d_out, int out_size)
{
    const int*   row_ptr     = (const int*)d_in[0];
    const int*   col_idx     = (const int*)d_in[1];
    const float* edge_weight = (const float*)d_in[2];
    const float* node_feat   = (const float*)d_in[3];
    float*       out         = (float*)d_out;

    int n_nodes = in_sizes[0] - 1;   // row_ptr has N+1 entries
    int n_edges = in_sizes[1];       // col_idx element count

    // k1: zero output rows + per-edge destination rows (warp per row)
    int b1 = (n_nodes * 32 + 255) / 256;
    fill_dst_kernel<<<b1, 256>>>(row_ptr, out, n_nodes);

    // k2: balanced edge-tile SpMM
    int tiles = (n_edges + TILE - 1) / TILE;
    int b2 = (tiles + WPB - 1) / WPB;
    spmm_balanced_kernel<<<b2, 32 * WPB>>>(col_idx, edge_weight,
                                           node_feat, out, n_edges);
}

// round 16
// speedup vs baseline: 1.5084x; 1.0011x over previous
#include <cuda_runtime.h>
#include <cuda_bf16.h>

// CSR multi-head SpMM: out[n,h,d] = sum_{e in row n} ew[e,h] * nf[col[e],h,d]
// N=50000, E=800000, H=8, D=8 -> 64 floats per row.
//
// R15 = R14 (28.7us: balanced 32-edge tiles, fused zero+fill, float2 RED)
//   + tile weights staged in SMEM: edge_weight for a tile is 1KB contiguous;
//     2 coalesced float4 LDGs/lane at stage time, inner loop reads weights
//     via conflict-free LDS (sweight[j*8+h], j const, h=lane>>2 -> 8 words
//     broadcast x4). Removes one LDG per edge from L1tex + scoreboard.

#define H 8
#define D 8
#define ROW_ELEMS (H * D)
#define TILE 32
#define WPB 4            // warps per block in spmm kernel
#define MAX_EDGES 800000

__device__ int g_dst[MAX_EDGES];

__global__ __launch_bounds__(256) void fill_dst_kernel(
    const int* __restrict__ row_ptr, float* __restrict__ out, int n_nodes)
{
    int warp = (blockIdx.x * blockDim.x + threadIdx.x) >> 5;
    int lane = threadIdx.x & 31;
    if (warp >= n_nodes) return;

    // zero this output row (accumulation target) - replaces memset node
    float2 z; z.x = 0.0f; z.y = 0.0f;
    *reinterpret_cast<float2*>(out + (size_t)warp * ROW_ELEMS + lane * 2) = z;

    int s = __ldg(&row_ptr[warp]);
    int e = __ldg(&row_ptr[warp + 1]);
    for (int j = s + lane; j < e; j += 32)
        g_dst[j] = warp;                    // coalesced, fire-and-forget
}

__global__ __launch_bounds__(32 * WPB) void spmm_balanced_kernel(
    const int* __restrict__ col_idx,
    const float* __restrict__ edge_weight,   // [E, 8]
    const float* __restrict__ node_feat,     // [N, 64]
    float* __restrict__ out,                 // [N, 64]
    int n_edges)
{
    __shared__ int   sdst[WPB][TILE];
    __shared__ int   scol[WPB][TILE];
    __shared__ float sweight[WPB][TILE * H];   // 1KB per warp tile

    int wip  = threadIdx.x >> 5;
    int lane = threadIdx.x & 31;
    int tile = blockIdx.x * WPB + wip;
    int base = tile * TILE;
    if (base >= n_edges) return;

    // stage this tile's 32 column indices + 32 destination rows (coalesced)
    int e   = base + lane;
    int idx = (e < n_edges) ? e : (n_edges - 1);
    scol[wip][lane] = __ldg(&col_idx[idx]);
    sdst[wip][lane] = __ldg(&g_dst[idx]);

    int h = lane >> 2;
    float ax = 0.0f, ay = 0.0f;

    if (base + TILE <= n_edges) {
        // stage this tile's weights: 256 contiguous floats = 64 float4
        {
            const float4* wsrc = reinterpret_cast<const float4*>(
                edge_weight + (size_t)base * H);
            float4* wdst = reinterpret_cast<float4*>(sweight[wip]);
            wdst[lane]      = __ldg(&wsrc[lane]);
            wdst[lane + 32] = __ldg(&wsrc[lane + 32]);
        }
        __syncwarp();

        #pragma unroll 4
        for (int j = 0; j < TILE; ++j) {
            int c   = scol[wip][j];                       // LDS broadcast
            float w = sweight[wip][j * H + h];            // LDS, conflict-free
            float2 f = *reinterpret_cast<const float2*>(
                node_feat + (size_t)c * ROW_ELEMS + lane * 2);
            ax = fmaf(w, f.x, ax);
            ay = fmaf(w, f.y, ay);
            // warp-uniform flush at segment boundary / tile end
            if (j == TILE - 1 || sdst[wip][j + 1] != sdst[wip][j]) {
                float2 v; v.x = ax; v.y = ay;
                atomicAdd(reinterpret_cast<float2*>(
                    out + (size_t)sdst[wip][j] * ROW_ELEMS + lane * 2), v);
                ax = 0.0f; ay = 0.0f;
            }
        }
    } else {
        __syncwarp();
        int nb = n_edges - base;
        for (int j = 0; j < nb; ++j) {
            int c   = scol[wip][j];
            float w = __ldg(&edge_weight[(size_t)(base + j) * H + h]);
            float2 f = *reinterpret_cast<const float2*>(
                node_feat + (size_t)c * ROW_ELEMS + lane * 2);
            ax = fmaf(w, f.x, ax);
            ay = fmaf(w, f.y, ay);
            if (j == nb - 1 || sdst[wip][j + 1] != sdst[wip][j]) {
                float2 v; v.x = ax; v.y = ay;
                atomicAdd(reinterpret_cast<float2*>(
                    out + (size_t)sdst[wip][j] * ROW_ELEMS + lane * 2), v);
                ax = 0.0f; ay = 0.0f;
            }
        }
    }
}

extern "C" void kernel_launch(void* const* d_in, const int* in_sizes, int n_in,
                              void* d_out, int out_size)
{
    const int*   row_ptr     = (const int*)d_in[0];
    const int*   col_idx     = (const int*)d_in[1];
    const float* edge_weight = (const float*)d_in[2];
    const float* node_feat   = (const float*)d_in[3];
    float*       out         = (float*)d_out;

    int n_nodes = in_sizes[0] - 1;   // row_ptr has N+1 entries
    int n_edges = in_sizes[1];       // col_idx element count

    // k1: zero output rows + per-edge destination rows (warp per row)
    int b1 = (n_nodes * 32 + 255) / 256;
    fill_dst_kernel<<<b1, 256>>>(row_ptr, out, n_nodes);

    // k2: balanced edge-tile SpMM
    int tiles = (n_edges + TILE - 1) / TILE;
    int b2 = (tiles + WPB - 1) / WPB;
    spmm_balanced_kernel<<<b2, 32 * WPB>>>(col_idx, edge_weight,
                                           node_feat, out, n_edges);
}